// round 9
// baseline (speedup 1.0000x reference)
#include <cuda_runtime.h>
#include <cstdint>

#define BSZ  4
#define NSEQ 2048
#define DIMC 1024
#define NH   16
#define DH   64
#define THREE_C 3072

// ---------------- scratch (no allocs allowed) ----------------
__device__ float g_Q[BSZ * NH * NSEQ * DH];   // [b,h,n,d]  (pre-scaled by 1/8)
__device__ float g_K[BSZ * NH * NSEQ * DH];
__device__ float g_V[BSZ * NH * NSEQ * DH];
__device__ float g_O[BSZ * NSEQ * DIMC];      // [b,n,h*64+d]
__device__ int   g_mask_is_i32;

// ---------------- mask dtype probe ----------------
__global__ void detect_mask_kernel(const unsigned* __restrict__ m) {
    __shared__ int bad;
    if (threadIdx.x == 0) bad = 0;
    __syncthreads();
    for (int i = threadIdx.x; i < 4096; i += 256)
        if (m[i] > 1u) bad = 1;
    __syncthreads();
    if (threadIdx.x == 0) g_mask_is_i32 = bad ? 0 : 1;
}

// ============ QKV GEMM: [8192,1024]@[1024,3072]+bias, scatter, Q scaled ============
// 128x128 tile, BK=16, 256 threads, 8x8 micro; double-buffered smem, 1 sync/tile.
__global__ __launch_bounds__(256, 2) void qkv_gemm_kernel(
    const float* __restrict__ X, const float* __restrict__ W, const float* __restrict__ bias)
{
    __shared__ float As[2][16][128];   // [buf][k][m]
    __shared__ float Bs[2][16][128];   // [buf][k][n]

    const int tid  = threadIdx.x;
    const int tx   = tid & 15, ty = tid >> 4;
    const int row0 = blockIdx.y * 128;
    const int col0 = blockIdx.x * 128;

    const int ra = tid >> 2;            // 0..63
    const int kc = (tid & 3) << 2;      // 0,4,8,12
    const int rb = tid >> 5;            // 0..7
    const int cb = (tid & 31) << 2;     // 0..124

    float acc[2][2][4][4];
#pragma unroll
    for (int ri = 0; ri < 2; ri++)
#pragma unroll
        for (int ci = 0; ci < 2; ci++)
#pragma unroll
            for (int i = 0; i < 4; i++)
#pragma unroll
                for (int j = 0; j < 4; j++) acc[ri][ci][i][j] = 0.f;

    // prefetch tile 0 and store into buf 0
    {
        float4 a0 = *(const float4*)&X[(row0 + ra) * DIMC + kc];
        float4 a1 = *(const float4*)&X[(row0 + ra + 64) * DIMC + kc];
        float4 b0 = *(const float4*)&W[rb * THREE_C + col0 + cb];
        float4 b1 = *(const float4*)&W[(rb + 8) * THREE_C + col0 + cb];
        As[0][kc + 0][ra] = a0.x; As[0][kc + 1][ra] = a0.y;
        As[0][kc + 2][ra] = a0.z; As[0][kc + 3][ra] = a0.w;
        As[0][kc + 0][ra + 64] = a1.x; As[0][kc + 1][ra + 64] = a1.y;
        As[0][kc + 2][ra + 64] = a1.z; As[0][kc + 3][ra + 64] = a1.w;
        *(float4*)&Bs[0][rb][cb]     = b0;
        *(float4*)&Bs[0][rb + 8][cb] = b1;
    }

    float4 pa0, pa1, pb0, pb1;
    for (int kt = 0; kt < 64; kt++) {
        const int buf = kt & 1;
        __syncthreads();                       // buf ready (stores from kt-1 done)
        if (kt < 63) {
            const int k0 = (kt + 1) * 16;
            pa0 = *(const float4*)&X[(row0 + ra) * DIMC + k0 + kc];
            pa1 = *(const float4*)&X[(row0 + ra + 64) * DIMC + k0 + kc];
            pb0 = *(const float4*)&W[(k0 + rb) * THREE_C + col0 + cb];
            pb1 = *(const float4*)&W[(k0 + rb + 8) * THREE_C + col0 + cb];
        }
#pragma unroll
        for (int kk = 0; kk < 16; kk++) {
            float4 af0 = *(const float4*)&As[buf][kk][ty * 4];
            float4 af1 = *(const float4*)&As[buf][kk][64 + ty * 4];
            float4 bf0 = *(const float4*)&Bs[buf][kk][tx * 4];
            float4 bf1 = *(const float4*)&Bs[buf][kk][64 + tx * 4];
            float ar[2][4] = {{af0.x, af0.y, af0.z, af0.w}, {af1.x, af1.y, af1.z, af1.w}};
            float br[2][4] = {{bf0.x, bf0.y, bf0.z, bf0.w}, {bf1.x, bf1.y, bf1.z, bf1.w}};
#pragma unroll
            for (int ri = 0; ri < 2; ri++)
#pragma unroll
                for (int ci = 0; ci < 2; ci++)
#pragma unroll
                    for (int i = 0; i < 4; i++)
#pragma unroll
                        for (int j = 0; j < 4; j++)
                            acc[ri][ci][i][j] += ar[ri][i] * br[ci][j];
        }
        if (kt < 63) {
            const int nb = buf ^ 1;
            As[nb][kc + 0][ra] = pa0.x; As[nb][kc + 1][ra] = pa0.y;
            As[nb][kc + 2][ra] = pa0.z; As[nb][kc + 3][ra] = pa0.w;
            As[nb][kc + 0][ra + 64] = pa1.x; As[nb][kc + 1][ra + 64] = pa1.y;
            As[nb][kc + 2][ra + 64] = pa1.z; As[nb][kc + 3][ra + 64] = pa1.w;
            *(float4*)&Bs[nb][rb][cb]     = pb0;
            *(float4*)&Bs[nb][rb + 8][cb] = pb1;
        }
    }

    // scatter: col c -> (three, head, d)
#pragma unroll
    for (int ri = 0; ri < 2; ri++)
#pragma unroll
        for (int i = 0; i < 4; i++) {
            const int r  = row0 + ri * 64 + ty * 4 + i;
            const int bb = r >> 11;
            const int n  = r & 2047;
#pragma unroll
            for (int ci = 0; ci < 2; ci++) {
                const int c     = col0 + ci * 64 + tx * 4;
                const int three = c >> 10;
                const int rem   = c & 1023;
                const int h     = rem >> 6;
                const int d     = rem & 63;
                float4 bv = *(const float4*)&bias[c];
                float4 v;
                v.x = acc[ri][ci][i][0] + bv.x;
                v.y = acc[ri][ci][i][1] + bv.y;
                v.z = acc[ri][ci][i][2] + bv.z;
                v.w = acc[ri][ci][i][3] + bv.w;
                if (three == 0) { v.x *= 0.125f; v.y *= 0.125f; v.z *= 0.125f; v.w *= 0.125f; }
                float* dst = (three == 0) ? g_Q : (three == 1) ? g_K : g_V;
                *(float4*)&dst[(((bb * NH + h) * NSEQ) + n) * DH + d] = v;
            }
        }
}

// ============ Flash attention (byte-identical logic to the passing kernel) ============
#define PS_STRIDE 68
#define ATT_SMEM ((64*128 + 64*64 + 64*64 + 128*PS_STRIDE) * 4 + 128*64)

__global__ __launch_bounds__(256, 2) void flash_attn_kernel(const void* __restrict__ mask)
{
    extern __shared__ float smf[];
    float*   Qtd = smf;                        // [64][128] d-major
    float*   Ktd = Qtd + 64 * 128;             // [64][64] d-major
    float*   Vs  = Ktd + 64 * 64;              // [64][64]
    float*   Ps  = Vs + 64 * 64;               // [128][68]
    uint8_t* Msh = (uint8_t*)(Ps + 128 * PS_STRIDE);

    const int b   = blockIdx.z;
    const int h   = blockIdx.y;
    const int q0  = blockIdx.x * 128;
    const int tid = threadIdx.x;
    const int tx  = tid & 15, ty = tid >> 4;

    const float* __restrict__ Qg = g_Q + ((b * NH + h) * NSEQ + q0) * DH;
    const float* __restrict__ Kb = g_K + (b * NH + h) * NSEQ * DH;
    const float* __restrict__ Vb = g_V + (b * NH + h) * NSEQ * DH;

#pragma unroll
    for (int it = 0; it < 8; it++) {
        const int idx = it * 256 + tid;
        const int r   = idx >> 4;
        const int dc  = (idx & 15) << 2;
        float4 v = *(const float4*)&Qg[r * DH + dc];
        Qtd[(dc + 0) * 128 + r] = v.x;
        Qtd[(dc + 1) * 128 + r] = v.y;
        Qtd[(dc + 2) * 128 + r] = v.z;
        Qtd[(dc + 3) * 128 + r] = v.w;
    }

    float mstate[8], lstate[8], O[8][4];
#pragma unroll
    for (int i = 0; i < 8; i++) {
        mstate[i] = -1e30f; lstate[i] = 0.f;
#pragma unroll
        for (int j = 0; j < 4; j++) O[i][j] = 0.f;
    }

    const int mi32 = g_mask_is_i32;
    const uint8_t* m8  = (const uint8_t*)mask;
    const int*     m32 = (const int*)mask;

    for (int kt = 0; kt < NSEQ; kt += 64) {
#pragma unroll
        for (int it = 0; it < 4; it++) {
            const int idx = it * 256 + tid;
            const int r   = idx >> 4;
            const int dc  = (idx & 15) << 2;
            float4 kv = *(const float4*)&Kb[(kt + r) * DH + dc];
            Ktd[(dc + 0) * 64 + r] = kv.x;
            Ktd[(dc + 1) * 64 + r] = kv.y;
            Ktd[(dc + 2) * 64 + r] = kv.z;
            Ktd[(dc + 3) * 64 + r] = kv.w;
            *(float4*)&Vs[r * 64 + dc] = *(const float4*)&Vb[(kt + r) * DH + dc];
        }
        const long mbase = ((long)b * NSEQ + q0) * NSEQ + kt;
        if (mi32) {
#pragma unroll 8
            for (int w = 0; w < 32; w++) {
                const int idx = w * 256 + tid;
                const int qr = idx >> 6, kc2 = idx & 63;
                Msh[idx] = (uint8_t)(m32[mbase + (long)qr * NSEQ + kc2] != 0);
            }
        } else {
#pragma unroll
            for (int w = 0; w < 8; w++) {
                const int idx = w * 256 + tid;
                const int qr = idx >> 4, wc = idx & 15;
                ((unsigned*)Msh)[idx] =
                    ((const unsigned*)(m8 + mbase + (long)qr * NSEQ))[wc];
            }
        }
        __syncthreads();

        float sacc[8][4];
#pragma unroll
        for (int i = 0; i < 8; i++)
#pragma unroll
            for (int j = 0; j < 4; j++) sacc[i][j] = 0.f;

#pragma unroll 8
        for (int d = 0; d < 64; d++) {
            float4 qf0 = *(const float4*)&Qtd[d * 128 + ty * 8];
            float4 qf1 = *(const float4*)&Qtd[d * 128 + ty * 8 + 4];
            float4 kf  = *(const float4*)&Ktd[d * 64 + tx * 4];
            float qa[8] = {qf0.x, qf0.y, qf0.z, qf0.w, qf1.x, qf1.y, qf1.z, qf1.w};
            float kb[4] = {kf.x, kf.y, kf.z, kf.w};
#pragma unroll
            for (int i = 0; i < 8; i++)
#pragma unroll
                for (int j = 0; j < 4; j++) sacc[i][j] += qa[i] * kb[j];
        }

#pragma unroll
        for (int i = 0; i < 8; i++) {
            const int r = ty * 8 + i;
            unsigned mu = *(const unsigned*)&Msh[r * 64 + tx * 4];
            float s0 = sacc[i][0], s1 = sacc[i][1], s2 = sacc[i][2], s3 = sacc[i][3];
            if (mu & 0x000000ffu) s0 = -3.4e38f;
            if (mu & 0x0000ff00u) s1 = -3.4e38f;
            if (mu & 0x00ff0000u) s2 = -3.4e38f;
            if (mu & 0xff000000u) s3 = -3.4e38f;
            float cm = fmaxf(fmaxf(s0, s1), fmaxf(s2, s3));
            cm = fmaxf(cm, __shfl_xor_sync(0xffffffffu, cm, 1));
            cm = fmaxf(cm, __shfl_xor_sync(0xffffffffu, cm, 2));
            cm = fmaxf(cm, __shfl_xor_sync(0xffffffffu, cm, 4));
            cm = fmaxf(cm, __shfl_xor_sync(0xffffffffu, cm, 8));
            const float nm    = fmaxf(mstate[i], cm);
            const float alpha = __expf(mstate[i] - nm);
            const float p0 = __expf(s0 - nm);
            const float p1 = __expf(s1 - nm);
            const float p2 = __expf(s2 - nm);
            const float p3 = __expf(s3 - nm);
            float ps = p0 + p1 + p2 + p3;
            ps += __shfl_xor_sync(0xffffffffu, ps, 1);
            ps += __shfl_xor_sync(0xffffffffu, ps, 2);
            ps += __shfl_xor_sync(0xffffffffu, ps, 4);
            ps += __shfl_xor_sync(0xffffffffu, ps, 8);
            lstate[i] = lstate[i] * alpha + ps;
            mstate[i] = nm;
            O[i][0] *= alpha; O[i][1] *= alpha; O[i][2] *= alpha; O[i][3] *= alpha;
            float4 pv = {p0, p1, p2, p3};
            *(float4*)&Ps[r * PS_STRIDE + tx * 4] = pv;
        }
        __syncthreads();

#pragma unroll 4
        for (int k4 = 0; k4 < 16; k4++) {
            float4 vf0 = *(const float4*)&Vs[(k4 * 4 + 0) * 64 + tx * 4];
            float4 vf1 = *(const float4*)&Vs[(k4 * 4 + 1) * 64 + tx * 4];
            float4 vf2 = *(const float4*)&Vs[(k4 * 4 + 2) * 64 + tx * 4];
            float4 vf3 = *(const float4*)&Vs[(k4 * 4 + 3) * 64 + tx * 4];
#pragma unroll
            for (int i = 0; i < 8; i++) {
                float4 pf = *(const float4*)&Ps[(ty * 8 + i) * PS_STRIDE + k4 * 4];
                O[i][0] += pf.x * vf0.x + pf.y * vf1.x + pf.z * vf2.x + pf.w * vf3.x;
                O[i][1] += pf.x * vf0.y + pf.y * vf1.y + pf.z * vf2.y + pf.w * vf3.y;
                O[i][2] += pf.x * vf0.z + pf.y * vf1.z + pf.z * vf2.z + pf.w * vf3.z;
                O[i][3] += pf.x * vf0.w + pf.y * vf1.w + pf.z * vf2.w + pf.w * vf3.w;
            }
        }
        __syncthreads();
    }

#pragma unroll
    for (int i = 0; i < 8; i++) {
        const float inv = 1.0f / lstate[i];
        const int r = q0 + ty * 8 + i;
        float4 ov = {O[i][0] * inv, O[i][1] * inv, O[i][2] * inv, O[i][3] * inv};
        *(float4*)&g_O[((b * NSEQ) + r) * DIMC + h * DH + tx * 4] = ov;
    }
}

// ============ Projection GEMM: double-buffered smem, 1 sync/tile ============
__global__ __launch_bounds__(256, 2) void proj_gemm_kernel(
    const float* __restrict__ W, const float* __restrict__ bias, float* __restrict__ out)
{
    __shared__ float As[2][16][128];
    __shared__ float Bs[2][16][128];

    const int tid  = threadIdx.x;
    const int tx   = tid & 15, ty = tid >> 4;
    const int row0 = blockIdx.y * 128;
    const int col0 = blockIdx.x * 128;

    const int ra = tid >> 2;
    const int kc = (tid & 3) << 2;
    const int rb = tid >> 5;
    const int cb = (tid & 31) << 2;

    float acc[2][2][4][4];
#pragma unroll
    for (int ri = 0; ri < 2; ri++)
#pragma unroll
        for (int ci = 0; ci < 2; ci++)
#pragma unroll
            for (int i = 0; i < 4; i++)
#pragma unroll
                for (int j = 0; j < 4; j++) acc[ri][ci][i][j] = 0.f;

    {
        float4 a0 = *(const float4*)&g_O[(row0 + ra) * DIMC + kc];
        float4 a1 = *(const float4*)&g_O[(row0 + ra + 64) * DIMC + kc];
        float4 b0 = *(const float4*)&W[rb * DIMC + col0 + cb];
        float4 b1 = *(const float4*)&W[(rb + 8) * DIMC + col0 + cb];
        As[0][kc + 0][ra] = a0.x; As[0][kc + 1][ra] = a0.y;
        As[0][kc + 2][ra] = a0.z; As[0][kc + 3][ra] = a0.w;
        As[0][kc + 0][ra + 64] = a1.x; As[0][kc + 1][ra + 64] = a1.y;
        As[0][kc + 2][ra + 64] = a1.z; As[0][kc + 3][ra + 64] = a1.w;
        *(float4*)&Bs[0][rb][cb]     = b0;
        *(float4*)&Bs[0][rb + 8][cb] = b1;
    }

    float4 pa0, pa1, pb0, pb1;
    for (int kt = 0; kt < 64; kt++) {
        const int buf = kt & 1;
        __syncthreads();
        if (kt < 63) {
            const int k0 = (kt + 1) * 16;
            pa0 = *(const float4*)&g_O[(row0 + ra) * DIMC + k0 + kc];
            pa1 = *(const float4*)&g_O[(row0 + ra + 64) * DIMC + k0 + kc];
            pb0 = *(const float4*)&W[(k0 + rb) * DIMC + col0 + cb];
            pb1 = *(const float4*)&W[(k0 + rb + 8) * DIMC + col0 + cb];
        }
#pragma unroll
        for (int kk = 0; kk < 16; kk++) {
            float4 af0 = *(const float4*)&As[buf][kk][ty * 4];
            float4 af1 = *(const float4*)&As[buf][kk][64 + ty * 4];
            float4 bf0 = *(const float4*)&Bs[buf][kk][tx * 4];
            float4 bf1 = *(const float4*)&Bs[buf][kk][64 + tx * 4];
            float ar[2][4] = {{af0.x, af0.y, af0.z, af0.w}, {af1.x, af1.y, af1.z, af1.w}};
            float br[2][4] = {{bf0.x, bf0.y, bf0.z, bf0.w}, {bf1.x, bf1.y, bf1.z, bf1.w}};
#pragma unroll
            for (int ri = 0; ri < 2; ri++)
#pragma unroll
                for (int ci = 0; ci < 2; ci++)
#pragma unroll
                    for (int i = 0; i < 4; i++)
#pragma unroll
                        for (int j = 0; j < 4; j++)
                            acc[ri][ci][i][j] += ar[ri][i] * br[ci][j];
        }
        if (kt < 63) {
            const int nb = buf ^ 1;
            As[nb][kc + 0][ra] = pa0.x; As[nb][kc + 1][ra] = pa0.y;
            As[nb][kc + 2][ra] = pa0.z; As[nb][kc + 3][ra] = pa0.w;
            As[nb][kc + 0][ra + 64] = pa1.x; As[nb][kc + 1][ra + 64] = pa1.y;
            As[nb][kc + 2][ra + 64] = pa1.z; As[nb][kc + 3][ra + 64] = pa1.w;
            *(float4*)&Bs[nb][rb][cb]     = pb0;
            *(float4*)&Bs[nb][rb + 8][cb] = pb1;
        }
    }

#pragma unroll
    for (int ri = 0; ri < 2; ri++)
#pragma unroll
        for (int i = 0; i < 4; i++) {
            const int r = row0 + ri * 64 + ty * 4 + i;
#pragma unroll
            for (int ci = 0; ci < 2; ci++) {
                const int c = col0 + ci * 64 + tx * 4;
                float4 bv = *(const float4*)&bias[c];
                float4 v;
                v.x = acc[ri][ci][i][0] + bv.x;
                v.y = acc[ri][ci][i][1] + bv.y;
                v.z = acc[ri][ci][i][2] + bv.z;
                v.w = acc[ri][ci][i][3] + bv.w;
                *(float4*)&out[r * DIMC + c] = v;
            }
        }
}

// ---------------- launch ----------------
extern "C" void kernel_launch(void* const* d_in, const int* in_sizes, int n_in,
                              void* d_out, int out_size)
{
    const float* x     = (const float*)d_in[0];
    const void*  mask  = d_in[1];
    const float* Wqkv  = (const float*)d_in[2];
    const float* bqkv  = (const float*)d_in[3];
    const float* Wproj = (const float*)d_in[4];
    const float* bproj = (const float*)d_in[5];
    float* out = (float*)d_out;

    cudaFuncSetAttribute(flash_attn_kernel,
                         cudaFuncAttributeMaxDynamicSharedMemorySize, ATT_SMEM);

    detect_mask_kernel<<<1, 256>>>((const unsigned*)mask);

    dim3 g1(THREE_C / 128, (BSZ * NSEQ) / 128);   // 24 x 64
    qkv_gemm_kernel<<<g1, 256>>>(x, Wqkv, bqkv);

    dim3 g2(NSEQ / 128, NH, BSZ);                 // 16 x 16 x 4
    flash_attn_kernel<<<g2, 256, ATT_SMEM>>>(mask);

    dim3 g3(DIMC / 128, (BSZ * NSEQ) / 128);      // 8 x 64
    proj_gemm_kernel<<<g3, 256>>>(Wproj, bproj, out);
}

// round 10
// speedup vs baseline: 1.0320x; 1.0320x over previous
#include <cuda_runtime.h>
#include <cstdint>

#define BSZ  4
#define NSEQ 2048
#define DIMC 1024
#define NH   16
#define DH   64
#define THREE_C 3072
#define NW (NSEQ / 64)     // mask words per row

typedef unsigned long long u64;

// ---------------- scratch (no allocs allowed) ----------------
__device__ float g_Q[BSZ * NH * DH * NSEQ];   // [b,h,d,n]  d-major! (pre-scaled 1/8)
__device__ float g_K[BSZ * NH * DH * NSEQ];   // [b,h,d,n]  d-major!
__device__ float g_V[BSZ * NH * NSEQ * DH];   // [b,h,n,d]
__device__ float g_O[BSZ * NSEQ * DIMC];      // [b,n,h*64+d]
__device__ u64   g_Mbits[BSZ * NSEQ * NW];    // bit=1 -> masked
__device__ int   g_mask_is_i32;

// ---------------- mask dtype probe ----------------
__global__ void detect_mask_kernel(const unsigned* __restrict__ m) {
    __shared__ int bad;
    if (threadIdx.x == 0) bad = 0;
    __syncthreads();
    for (int i = threadIdx.x; i < 4096; i += 256)
        if (m[i] > 1u) bad = 1;
    __syncthreads();
    if (threadIdx.x == 0) g_mask_is_i32 = bad ? 0 : 1;
}

// ---------------- mask bit-pack: one warp per row ----------------
__global__ __launch_bounds__(256) void pack_mask_kernel(const void* __restrict__ mask) {
    const int warp = (blockIdx.x * 256 + threadIdx.x) >> 5;   // row 0..8191
    const int lane = threadIdx.x & 31;
    const int mi32 = g_mask_is_i32;
    if (mi32) {
        const int* m = (const int*)mask + (size_t)warp * NSEQ;
#pragma unroll 4
        for (int w = 0; w < NW; w++) {
            unsigned b0 = __ballot_sync(0xffffffffu, m[w * 64 + lane] != 0);
            unsigned b1 = __ballot_sync(0xffffffffu, m[w * 64 + 32 + lane] != 0);
            if (lane == 0) g_Mbits[warp * NW + w] = (u64)b0 | ((u64)b1 << 32);
        }
    } else {
        const uint8_t* m = (const uint8_t*)mask + (size_t)warp * NSEQ;
#pragma unroll 4
        for (int w = 0; w < NW; w++) {
            unsigned b0 = __ballot_sync(0xffffffffu, m[w * 64 + lane] != 0);
            unsigned b1 = __ballot_sync(0xffffffffu, m[w * 64 + 32 + lane] != 0);
            if (lane == 0) g_Mbits[warp * NW + w] = (u64)b0 | ((u64)b1 << 32);
        }
    }
}

// ============ QKV GEMM (R7 body; Q/K stored d-major) ============
__global__ __launch_bounds__(256, 2) void qkv_gemm_kernel(
    const float* __restrict__ X, const float* __restrict__ W, const float* __restrict__ bias)
{
    __shared__ float As[16][128];
    __shared__ float Bs[16][128];

    const int tid  = threadIdx.x;
    const int tx   = tid & 15, ty = tid >> 4;
    const int row0 = blockIdx.y * 128;
    const int col0 = blockIdx.x * 128;

    const int ra = tid >> 2;
    const int kc = (tid & 3) << 2;
    const int rb = tid >> 5;
    const int cb = (tid & 31) << 2;

    float acc[2][2][4][4];
#pragma unroll
    for (int ri = 0; ri < 2; ri++)
#pragma unroll
        for (int ci = 0; ci < 2; ci++)
#pragma unroll
            for (int i = 0; i < 4; i++)
#pragma unroll
                for (int j = 0; j < 4; j++) acc[ri][ci][i][j] = 0.f;

    float4 pa0 = *(const float4*)&X[(row0 + ra) * DIMC + kc];
    float4 pa1 = *(const float4*)&X[(row0 + ra + 64) * DIMC + kc];
    float4 pb0 = *(const float4*)&W[rb * THREE_C + col0 + cb];
    float4 pb1 = *(const float4*)&W[(rb + 8) * THREE_C + col0 + cb];

    for (int kt = 0; kt < 64; kt++) {
        As[kc + 0][ra] = pa0.x; As[kc + 1][ra] = pa0.y;
        As[kc + 2][ra] = pa0.z; As[kc + 3][ra] = pa0.w;
        As[kc + 0][ra + 64] = pa1.x; As[kc + 1][ra + 64] = pa1.y;
        As[kc + 2][ra + 64] = pa1.z; As[kc + 3][ra + 64] = pa1.w;
        *(float4*)&Bs[rb][cb]     = pb0;
        *(float4*)&Bs[rb + 8][cb] = pb1;
        __syncthreads();
        if (kt < 63) {
            const int k0 = (kt + 1) * 16;
            pa0 = *(const float4*)&X[(row0 + ra) * DIMC + k0 + kc];
            pa1 = *(const float4*)&X[(row0 + ra + 64) * DIMC + k0 + kc];
            pb0 = *(const float4*)&W[(k0 + rb) * THREE_C + col0 + cb];
            pb1 = *(const float4*)&W[(k0 + rb + 8) * THREE_C + col0 + cb];
        }
#pragma unroll
        for (int kk = 0; kk < 16; kk++) {
            float4 af0 = *(const float4*)&As[kk][ty * 4];
            float4 af1 = *(const float4*)&As[kk][64 + ty * 4];
            float4 bf0 = *(const float4*)&Bs[kk][tx * 4];
            float4 bf1 = *(const float4*)&Bs[kk][64 + tx * 4];
            float ar[2][4] = {{af0.x, af0.y, af0.z, af0.w}, {af1.x, af1.y, af1.z, af1.w}};
            float br[2][4] = {{bf0.x, bf0.y, bf0.z, bf0.w}, {bf1.x, bf1.y, bf1.z, bf1.w}};
#pragma unroll
            for (int ri = 0; ri < 2; ri++)
#pragma unroll
                for (int ci = 0; ci < 2; ci++)
#pragma unroll
                    for (int i = 0; i < 4; i++)
#pragma unroll
                        for (int j = 0; j < 4; j++)
                            acc[ri][ci][i][j] += ar[ri][i] * br[ci][j];
        }
        __syncthreads();
    }

#pragma unroll
    for (int ri = 0; ri < 2; ri++)
#pragma unroll
        for (int i = 0; i < 4; i++) {
            const int r  = row0 + ri * 64 + ty * 4 + i;
            const int bb = r >> 11;
            const int n  = r & 2047;
#pragma unroll
            for (int ci = 0; ci < 2; ci++) {
                const int c     = col0 + ci * 64 + tx * 4;
                const int three = c >> 10;
                const int rem   = c & 1023;
                const int h     = rem >> 6;
                const int d     = rem & 63;
                float4 bv = *(const float4*)&bias[c];
                float4 v;
                v.x = acc[ri][ci][i][0] + bv.x;
                v.y = acc[ri][ci][i][1] + bv.y;
                v.z = acc[ri][ci][i][2] + bv.z;
                v.w = acc[ri][ci][i][3] + bv.w;
                if (three == 2) {
                    *(float4*)&g_V[(((bb * NH + h) * NSEQ) + n) * DH + d] = v;
                } else {
                    float sc = 1.0f;
                    float* dst = g_K;
                    if (three == 0) { sc = 0.125f; dst = g_Q; }
                    const int base = ((bb * NH + h) * DH + d) * NSEQ + n;
                    dst[base]            = v.x * sc;
                    dst[base + NSEQ]     = v.y * sc;
                    dst[base + 2 * NSEQ] = v.z * sc;
                    dst[base + 3 * NSEQ] = v.w * sc;
                }
            }
        }
}

// ============ Flash attention: 128 thr, 8x8 micro-tile, bitmask, reg prefetch ============
// smem (floats): Qtd[64][128] @0, Kt[64][64] @8192, Vs[64][64] @12288, Ps[128][68] @16384
#define ATT_SMEM ((8192 + 4096 + 4096 + 128 * 68) * 4)   // 100352 B

__global__ __launch_bounds__(128, 2) void flash_attn_kernel()
{
    extern __shared__ float smf[];
    float* Qtd = smf;            // [64][128] d-major
    float* Kt  = smf + 8192;     // [64][64]  d-major
    float* Vs  = smf + 12288;    // [64][64]  key-major
    float* Ps  = smf + 16384;    // [128][68]

    const int b   = blockIdx.z;
    const int h   = blockIdx.y;
    const int q0  = blockIdx.x * 128;
    const int tid = threadIdx.x;
    const int tx  = tid & 7;     // key/col octet
    const int ty  = tid >> 3;    // row group, 16

    const int bh = b * NH + h;
    const float* __restrict__ Qg = g_Q + (size_t)bh * DH * NSEQ;
    const float* __restrict__ Kg = g_K + (size_t)bh * DH * NSEQ;
    const float* __restrict__ Vg = g_V + (size_t)bh * NSEQ * DH;
    const u64*   __restrict__ Mb = g_Mbits + ((size_t)b * NSEQ + q0) * NW;

    // Q tile load (coalesced, d-major, no transpose)
#pragma unroll
    for (int it = 0; it < 16; it++) {
        const int idx = it * 128 + tid;       // 0..2047 float4
        const int d   = idx >> 5;
        const int r4  = (idx & 31) << 2;
        *(float4*)&Qtd[d * 128 + r4] = *(const float4*)&Qg[d * NSEQ + q0 + r4];
    }

    float mst[8], lst[8], O[8][8];
#pragma unroll
    for (int i = 0; i < 8; i++) {
        mst[i] = -1e30f; lst[i] = 0.f;
#pragma unroll
        for (int c = 0; c < 8; c++) O[i][c] = 0.f;
    }

    // preload tile 0 K/V
    float4 rK[8], rV[8];
#pragma unroll
    for (int it = 0; it < 8; it++) {
        const int idx = it * 128 + tid;       // 0..1023 float4
        const int r   = idx >> 4;
        const int c4  = (idx & 15) << 2;
        rK[it] = *(const float4*)&Kg[r * NSEQ + c4];
        rV[it] = *(const float4*)&Vg[r * DH + c4];
    }

    for (int t = 0; t < NW; t++) {
        __syncthreads();   // previous tile's smem reads complete
        // store prefetched K/V tile
#pragma unroll
        for (int it = 0; it < 8; it++) {
            const int idx = it * 128 + tid;
            const int r   = idx >> 4;
            const int c4  = (idx & 15) << 2;
            *(float4*)&Kt[r * 64 + c4] = rK[it];
            *(float4*)&Vs[r * 64 + c4] = rV[it];
        }
        // mask words for this thread's 8 rows
        u64 wd[8];
#pragma unroll
        for (int i = 0; i < 8; i++)
            wd[i] = Mb[(ty * 8 + i) * NW + t];
        __syncthreads();   // tile ready

        // ---- S = Q K^T ----
        float sacc[8][8];
#pragma unroll
        for (int i = 0; i < 8; i++)
#pragma unroll
            for (int j = 0; j < 8; j++) sacc[i][j] = 0.f;

#pragma unroll 2
        for (int d = 0; d < 64; d++) {
            float4 qa0 = *(const float4*)&Qtd[d * 128 + ty * 8];
            float4 qa1 = *(const float4*)&Qtd[d * 128 + ty * 8 + 4];
            float4 kb0 = *(const float4*)&Kt[d * 64 + tx * 8];
            float4 kb1 = *(const float4*)&Kt[d * 64 + tx * 8 + 4];
            float qa[8] = {qa0.x, qa0.y, qa0.z, qa0.w, qa1.x, qa1.y, qa1.z, qa1.w};
            float kb[8] = {kb0.x, kb0.y, kb0.z, kb0.w, kb1.x, kb1.y, kb1.z, kb1.w};
#pragma unroll
            for (int i = 0; i < 8; i++)
#pragma unroll
                for (int j = 0; j < 8; j++)
                    sacc[i][j] += qa[i] * kb[j];
        }

        // prefetch next tile's K/V (hidden under softmax + PV)
        if (t < NW - 1) {
            const int kt1 = (t + 1) * 64;
#pragma unroll
            for (int it = 0; it < 8; it++) {
                const int idx = it * 128 + tid;
                const int r   = idx >> 4;
                const int c4  = (idx & 15) << 2;
                rK[it] = *(const float4*)&Kg[r * NSEQ + kt1 + c4];
                rV[it] = *(const float4*)&Vg[(kt1 + r) * DH + c4];
            }
        }

        // ---- online softmax + write P ----
#pragma unroll
        for (int i = 0; i < 8; i++) {
            const unsigned mb = (unsigned)(wd[i] >> (tx * 8)) & 0xffu;
            float s[8];
#pragma unroll
            for (int j = 0; j < 8; j++)
                s[j] = (mb & (1u << j)) ? -3.4e38f : sacc[i][j];
            float cm = s[0];
#pragma unroll
            for (int j = 1; j < 8; j++) cm = fmaxf(cm, s[j]);
            cm = fmaxf(cm, __shfl_xor_sync(0xffffffffu, cm, 1));
            cm = fmaxf(cm, __shfl_xor_sync(0xffffffffu, cm, 2));
            cm = fmaxf(cm, __shfl_xor_sync(0xffffffffu, cm, 4));
            const float nm    = fmaxf(mst[i], cm);
            const float alpha = __expf(mst[i] - nm);
            float p[8], psum = 0.f;
#pragma unroll
            for (int j = 0; j < 8; j++) { p[j] = __expf(s[j] - nm); psum += p[j]; }
            lst[i] = lst[i] * alpha + psum;   // partial over tx; reduced at end
            mst[i] = nm;
#pragma unroll
            for (int c = 0; c < 8; c++) O[i][c] *= alpha;
            float4 pv0 = {p[0], p[1], p[2], p[3]};
            float4 pv1 = {p[4], p[5], p[6], p[7]};
            *(float4*)&Ps[(ty * 8 + i) * 68 + tx * 8]     = pv0;
            *(float4*)&Ps[(ty * 8 + i) * 68 + tx * 8 + 4] = pv1;
        }
        __syncwarp();   // P rows of this ty-group are warp-local

        // ---- O += P V ----
#pragma unroll 2
        for (int k4 = 0; k4 < 16; k4++) {
            float va[4][8];
#pragma unroll
            for (int k = 0; k < 4; k++) {
                float4 v0 = *(const float4*)&Vs[(k4 * 4 + k) * 64 + tx * 8];
                float4 v1 = *(const float4*)&Vs[(k4 * 4 + k) * 64 + tx * 8 + 4];
                va[k][0] = v0.x; va[k][1] = v0.y; va[k][2] = v0.z; va[k][3] = v0.w;
                va[k][4] = v1.x; va[k][5] = v1.y; va[k][6] = v1.z; va[k][7] = v1.w;
            }
#pragma unroll
            for (int i = 0; i < 8; i++) {
                float4 pf = *(const float4*)&Ps[(ty * 8 + i) * 68 + k4 * 4];
#pragma unroll
                for (int c = 0; c < 8; c++)
                    O[i][c] += pf.x * va[0][c] + pf.y * va[1][c]
                             + pf.z * va[2][c] + pf.w * va[3][c];
            }
        }
    }

    // final: reduce l over the 8 tx lanes, write out
#pragma unroll
    for (int i = 0; i < 8; i++) {
        float l = lst[i];
        l += __shfl_xor_sync(0xffffffffu, l, 1);
        l += __shfl_xor_sync(0xffffffffu, l, 2);
        l += __shfl_xor_sync(0xffffffffu, l, 4);
        const float inv = 1.0f / l;
        const int r = q0 + ty * 8 + i;
        float4 o0 = {O[i][0] * inv, O[i][1] * inv, O[i][2] * inv, O[i][3] * inv};
        float4 o1 = {O[i][4] * inv, O[i][5] * inv, O[i][6] * inv, O[i][7] * inv};
        float* op = &g_O[(size_t)(b * NSEQ + r) * DIMC + h * DH + tx * 8];
        *(float4*)op       = o0;
        *(float4*)(op + 4) = o1;
    }
}

// ============ Projection GEMM (R7 body, unchanged) ============
__global__ __launch_bounds__(256, 2) void proj_gemm_kernel(
    const float* __restrict__ W, const float* __restrict__ bias, float* __restrict__ out)
{
    __shared__ float As[16][128];
    __shared__ float Bs[16][128];

    const int tid  = threadIdx.x;
    const int tx   = tid & 15, ty = tid >> 4;
    const int row0 = blockIdx.y * 128;
    const int col0 = blockIdx.x * 128;

    const int ra = tid >> 2;
    const int kc = (tid & 3) << 2;
    const int rb = tid >> 5;
    const int cb = (tid & 31) << 2;

    float acc[2][2][4][4];
#pragma unroll
    for (int ri = 0; ri < 2; ri++)
#pragma unroll
        for (int ci = 0; ci < 2; ci++)
#pragma unroll
            for (int i = 0; i < 4; i++)
#pragma unroll
                for (int j = 0; j < 4; j++) acc[ri][ci][i][j] = 0.f;

    float4 pa0 = *(const float4*)&g_O[(row0 + ra) * DIMC + kc];
    float4 pa1 = *(const float4*)&g_O[(row0 + ra + 64) * DIMC + kc];
    float4 pb0 = *(const float4*)&W[rb * DIMC + col0 + cb];
    float4 pb1 = *(const float4*)&W[(rb + 8) * DIMC + col0 + cb];

    for (int kt = 0; kt < 64; kt++) {
        As[kc + 0][ra] = pa0.x; As[kc + 1][ra] = pa0.y;
        As[kc + 2][ra] = pa0.z; As[kc + 3][ra] = pa0.w;
        As[kc + 0][ra + 64] = pa1.x; As[kc + 1][ra + 64] = pa1.y;
        As[kc + 2][ra + 64] = pa1.z; As[kc + 3][ra + 64] = pa1.w;
        *(float4*)&Bs[rb][cb]     = pb0;
        *(float4*)&Bs[rb + 8][cb] = pb1;
        __syncthreads();
        if (kt < 63) {
            const int k0 = (kt + 1) * 16;
            pa0 = *(const float4*)&g_O[(row0 + ra) * DIMC + k0 + kc];
            pa1 = *(const float4*)&g_O[(row0 + ra + 64) * DIMC + k0 + kc];
            pb0 = *(const float4*)&W[(k0 + rb) * DIMC + col0 + cb];
            pb1 = *(const float4*)&W[(k0 + rb + 8) * DIMC + col0 + cb];
        }
#pragma unroll
        for (int kk = 0; kk < 16; kk++) {
            float4 af0 = *(const float4*)&As[kk][ty * 4];
            float4 af1 = *(const float4*)&As[kk][64 + ty * 4];
            float4 bf0 = *(const float4*)&Bs[kk][tx * 4];
            float4 bf1 = *(const float4*)&Bs[kk][64 + tx * 4];
            float ar[2][4] = {{af0.x, af0.y, af0.z, af0.w}, {af1.x, af1.y, af1.z, af1.w}};
            float br[2][4] = {{bf0.x, bf0.y, bf0.z, bf0.w}, {bf1.x, bf1.y, bf1.z, bf1.w}};
#pragma unroll
            for (int ri = 0; ri < 2; ri++)
#pragma unroll
                for (int ci = 0; ci < 2; ci++)
#pragma unroll
                    for (int i = 0; i < 4; i++)
#pragma unroll
                        for (int j = 0; j < 4; j++)
                            acc[ri][ci][i][j] += ar[ri][i] * br[ci][j];
        }
        __syncthreads();
    }

#pragma unroll
    for (int ri = 0; ri < 2; ri++)
#pragma unroll
        for (int i = 0; i < 4; i++) {
            const int r = row0 + ri * 64 + ty * 4 + i;
#pragma unroll
            for (int ci = 0; ci < 2; ci++) {
                const int c = col0 + ci * 64 + tx * 4;
                float4 bv = *(const float4*)&bias[c];
                float4 v;
                v.x = acc[ri][ci][i][0] + bv.x;
                v.y = acc[ri][ci][i][1] + bv.y;
                v.z = acc[ri][ci][i][2] + bv.z;
                v.w = acc[ri][ci][i][3] + bv.w;
                *(float4*)&out[r * DIMC + c] = v;
            }
        }
}

// ---------------- launch ----------------
extern "C" void kernel_launch(void* const* d_in, const int* in_sizes, int n_in,
                              void* d_out, int out_size)
{
    const float* x     = (const float*)d_in[0];
    const void*  mask  = d_in[1];
    const float* Wqkv  = (const float*)d_in[2];
    const float* bqkv  = (const float*)d_in[3];
    const float* Wproj = (const float*)d_in[4];
    const float* bproj = (const float*)d_in[5];
    float* out = (float*)d_out;

    cudaFuncSetAttribute(flash_attn_kernel,
                         cudaFuncAttributeMaxDynamicSharedMemorySize, ATT_SMEM);

    detect_mask_kernel<<<1, 256>>>((const unsigned*)mask);
    pack_mask_kernel<<<(BSZ * NSEQ) / 8, 256>>>(mask);

    dim3 g1(THREE_C / 128, (BSZ * NSEQ) / 128);   // 24 x 64
    qkv_gemm_kernel<<<g1, 256>>>(x, Wqkv, bqkv);

    dim3 g2(NSEQ / 128, NH, BSZ);                 // 16 x 16 x 4
    flash_attn_kernel<<<g2, 128, ATT_SMEM>>>();

    dim3 g3(DIMC / 128, (BSZ * NSEQ) / 128);      // 8 x 64
    proj_gemm_kernel<<<g3, 256>>>(Wproj, bproj, out);
}